// round 1
// baseline (speedup 1.0000x reference)
#include <cuda_runtime.h>

// Problem constants (fixed by the reference setup_inputs)
#define BB      4
#define CC      96
#define HH      192
#define WW      320
#define HW      (HH * WW)          // 61440
#define HW4     (HW / 4)           // 15360 float4 per (b, plane)
#define OUT_CH  81

// corr[b,h,w] = (sum_c f1*f2) * mask / C ; mask = (sum_c |f1| > 0.1)
// out[b,oc,h,w] = corr[b,h,w] for all 81 oc.
__global__ __launch_bounds__(256) void spike_corr_kernel(
    const float4* __restrict__ f1,
    const float4* __restrict__ f2,
    float4* __restrict__ out)
{
    int i = blockIdx.x * blockDim.x + threadIdx.x;   // [0, BB*HW4)
    if (i >= BB * HW4) return;

    int b = i / HW4;
    int p = i - b * HW4;

    const float4* __restrict__ f1p = f1 + (size_t)b * CC * HW4 + p;
    const float4* __restrict__ f2p = f2 + (size_t)b * CC * HW4 + p;

    float dx = 0.f, dy = 0.f, dz = 0.f, dw = 0.f;
    float ax = 0.f, ay = 0.f, az = 0.f, aw = 0.f;

#pragma unroll 8
    for (int c = 0; c < CC; ++c) {
        float4 a = __ldg(f1p + (size_t)c * HW4);
        float4 v = __ldg(f2p + (size_t)c * HW4);
        dx = fmaf(a.x, v.x, dx);
        dy = fmaf(a.y, v.y, dy);
        dz = fmaf(a.z, v.z, dz);
        dw = fmaf(a.w, v.w, dw);
        ax += fabsf(a.x);
        ay += fabsf(a.y);
        az += fabsf(a.z);
        aw += fabsf(a.w);
    }

    const float inv_c = 1.0f / (float)CC;
    float4 r;
    r.x = (ax > 0.1f) ? dx * inv_c : 0.0f;
    r.y = (ay > 0.1f) ? dy * inv_c : 0.0f;
    r.z = (az > 0.1f) ? dz * inv_c : 0.0f;
    r.w = (aw > 0.1f) ? dw * inv_c : 0.0f;

    float4* __restrict__ op = out + (size_t)b * OUT_CH * HW4 + p;
#pragma unroll
    for (int oc = 0; oc < OUT_CH; ++oc) {
        op[(size_t)oc * HW4] = r;
    }
}

extern "C" void kernel_launch(void* const* d_in, const int* in_sizes, int n_in,
                              void* d_out, int out_size)
{
    const float4* f1 = (const float4*)d_in[0];
    const float4* f2 = (const float4*)d_in[1];
    float4* out = (float4*)d_out;

    const int total = BB * HW4;                 // 61440 threads
    const int threads = 256;
    const int blocks = (total + threads - 1) / threads;  // 240
    spike_corr_kernel<<<blocks, threads>>>(f1, f2, out);
}

// round 2
// speedup vs baseline: 1.4937x; 1.4937x over previous
#include <cuda_runtime.h>

// Problem constants (fixed by the reference setup_inputs)
#define BB      4
#define CC      96
#define HH      192
#define WW      320
#define HW      (HH * WW)          // 61440
#define HW4     (HW / 4)           // 15360 float4 per (b, plane)
#define OUT_CH  81

#define PIXB    128                // float4-pixels per block (threadIdx.x)
#define CSPLIT  4                  // channel splits per pixel (threadIdx.y)
#define CPER    (CC / CSPLIT)      // 24 channels per thread

// corr[b,h,w] = (sum_c f1*f2) * mask / C ; mask = (sum_c |f1| > 0.1)
// out[b,oc,h,w] = corr[b,h,w] for all 81 oc.
__global__ __launch_bounds__(PIXB * CSPLIT) void spike_corr_kernel(
    const float4* __restrict__ f1,
    const float4* __restrict__ f2,
    float4* __restrict__ out)
{
    __shared__ float4 s_dot[CSPLIT][PIXB];
    __shared__ float4 s_abs[CSPLIT][PIXB];

    const int x = threadIdx.x;                 // pixel slot within block
    const int y = threadIdx.y;                 // channel quarter
    const int px = blockIdx.x * PIXB + x;      // global float4-pixel [0, BB*HW4)

    const int b = px / HW4;
    const int p = px - b * HW4;

    const size_t base = (size_t)b * CC * HW4 + (size_t)(y * CPER) * HW4 + p;
    const float4* __restrict__ f1p = f1 + base;
    const float4* __restrict__ f2p = f2 + base;

    float dx = 0.f, dy = 0.f, dz = 0.f, dw = 0.f;
    float ax = 0.f, ay = 0.f, az = 0.f, aw = 0.f;

#pragma unroll
    for (int c = 0; c < CPER; ++c) {
        float4 a = __ldg(f1p + (size_t)c * HW4);
        float4 v = __ldg(f2p + (size_t)c * HW4);
        dx = fmaf(a.x, v.x, dx);
        dy = fmaf(a.y, v.y, dy);
        dz = fmaf(a.z, v.z, dz);
        dw = fmaf(a.w, v.w, dw);
        ax += fabsf(a.x);
        ay += fabsf(a.y);
        az += fabsf(a.z);
        aw += fabsf(a.w);
    }

    s_dot[y][x] = make_float4(dx, dy, dz, dw);
    s_abs[y][x] = make_float4(ax, ay, az, aw);
    __syncthreads();

    // Every thread (all 4 y's) redundantly reduces its pixel's 4 partials,
    // so each y can independently store its share of the 81 output channels.
    float4 d0 = s_dot[0][x], d1 = s_dot[1][x], d2 = s_dot[2][x], d3 = s_dot[3][x];
    float4 a0 = s_abs[0][x], a1 = s_abs[1][x], a2 = s_abs[2][x], a3 = s_abs[3][x];

    float fdx = d0.x + d1.x + d2.x + d3.x;
    float fdy = d0.y + d1.y + d2.y + d3.y;
    float fdz = d0.z + d1.z + d2.z + d3.z;
    float fdw = d0.w + d1.w + d2.w + d3.w;
    float fax = a0.x + a1.x + a2.x + a3.x;
    float fay = a0.y + a1.y + a2.y + a3.y;
    float faz = a0.z + a1.z + a2.z + a3.z;
    float faw = a0.w + a1.w + a2.w + a3.w;

    const float inv_c = 1.0f / (float)CC;
    float4 r;
    r.x = (fax > 0.1f) ? fdx * inv_c : 0.0f;
    r.y = (fay > 0.1f) ? fdy * inv_c : 0.0f;
    r.z = (faz > 0.1f) ? fdz * inv_c : 0.0f;
    r.w = (faw > 0.1f) ? fdw * inv_c : 0.0f;

    float4* __restrict__ op = out + (size_t)b * OUT_CH * HW4 + p;
    // y-th thread stores channels y, y+4, y+8, ... (~20-21 stores each)
#pragma unroll
    for (int oc = y; oc < OUT_CH; oc += CSPLIT) {
        op[(size_t)oc * HW4] = r;
    }
}

extern "C" void kernel_launch(void* const* d_in, const int* in_sizes, int n_in,
                              void* d_out, int out_size)
{
    const float4* f1 = (const float4*)d_in[0];
    const float4* f2 = (const float4*)d_in[1];
    float4* out = (float4*)d_out;

    dim3 block(PIXB, CSPLIT);                  // 512 threads
    dim3 grid((BB * HW4) / PIXB);              // 480 blocks
    spike_corr_kernel<<<grid, block>>>(f1, f2, out);
}

// round 3
// speedup vs baseline: 1.5282x; 1.0231x over previous
#include <cuda_runtime.h>

// Problem constants (fixed by the reference setup_inputs)
#define BB      4
#define CC      96
#define HH      192
#define WW      320
#define HW      (HH * WW)          // 61440
#define HW4     (HW / 4)           // 15360 float4 per (b, plane)
#define OUT_CH  81

#define PIXB    32                 // float4-pixels per block (threadIdx.x)
#define CSPLIT  8                  // channel splits per pixel (threadIdx.y)
#define CPER    (CC / CSPLIT)      // 12 channels per thread

// corr[b,h,w] = (sum_c f1*f2) * mask / C ; mask = (sum_c |f1| > 0.1)
// out[b,oc,h,w] = corr[b,h,w] for all 81 oc.
__global__ __launch_bounds__(PIXB * CSPLIT) void spike_corr_kernel(
    const float4* __restrict__ f1,
    const float4* __restrict__ f2,
    float4* __restrict__ out)
{
    __shared__ float4 s_dot[CSPLIT][PIXB];
    __shared__ float4 s_abs[CSPLIT][PIXB];

    const int x = threadIdx.x;                 // pixel slot within block
    const int y = threadIdx.y;                 // channel slice
    const int px = blockIdx.x * PIXB + x;      // global float4-pixel [0, BB*HW4)

    const int b = px / HW4;                    // HW4 % PIXB == 0 -> uniform per block
    const int p = px - b * HW4;

    const size_t base = (size_t)b * CC * HW4 + (size_t)(y * CPER) * HW4 + p;
    const float4* __restrict__ f1p = f1 + base;
    const float4* __restrict__ f2p = f2 + base;

    float dx = 0.f, dy = 0.f, dz = 0.f, dw = 0.f;
    float ax = 0.f, ay = 0.f, az = 0.f, aw = 0.f;

#pragma unroll
    for (int c = 0; c < CPER; ++c) {
        float4 a = __ldcs(f1p + (size_t)c * HW4);
        float4 v = __ldcs(f2p + (size_t)c * HW4);
        dx = fmaf(a.x, v.x, dx);
        dy = fmaf(a.y, v.y, dy);
        dz = fmaf(a.z, v.z, dz);
        dw = fmaf(a.w, v.w, dw);
        ax += fabsf(a.x);
        ay += fabsf(a.y);
        az += fabsf(a.z);
        aw += fabsf(a.w);
    }

    s_dot[y][x] = make_float4(dx, dy, dz, dw);
    s_abs[y][x] = make_float4(ax, ay, az, aw);
    __syncthreads();

    // Every thread (all 8 y's) redundantly reduces its pixel's 8 partials,
    // so each y can independently store its share of the 81 output channels.
    float fdx = 0.f, fdy = 0.f, fdz = 0.f, fdw = 0.f;
    float fax = 0.f, fay = 0.f, faz = 0.f, faw = 0.f;
#pragma unroll
    for (int k = 0; k < CSPLIT; ++k) {
        float4 d = s_dot[k][x];
        float4 a = s_abs[k][x];
        fdx += d.x; fdy += d.y; fdz += d.z; fdw += d.w;
        fax += a.x; fay += a.y; faz += a.z; faw += a.w;
    }

    const float inv_c = 1.0f / (float)CC;
    float4 r;
    r.x = (fax > 0.1f) ? fdx * inv_c : 0.0f;
    r.y = (fay > 0.1f) ? fdy * inv_c : 0.0f;
    r.z = (faz > 0.1f) ? fdz * inv_c : 0.0f;
    r.w = (faw > 0.1f) ? fdw * inv_c : 0.0f;

    float4* __restrict__ op = out + (size_t)b * OUT_CH * HW4 + p;
    // y-th thread stores channels y, y+8, y+16, ... (10-11 stores each)
#pragma unroll
    for (int oc = y; oc < OUT_CH; oc += CSPLIT) {
        __stcs(op + (size_t)oc * HW4, r);
    }
}

extern "C" void kernel_launch(void* const* d_in, const int* in_sizes, int n_in,
                              void* d_out, int out_size)
{
    const float4* f1 = (const float4*)d_in[0];
    const float4* f2 = (const float4*)d_in[1];
    float4* out = (float4*)d_out;

    dim3 block(PIXB, CSPLIT);                  // 256 threads
    dim3 grid((BB * HW4) / PIXB);              // 1920 blocks
    spike_corr_kernel<<<grid, block>>>(f1, f2, out);
}